// round 7
// baseline (speedup 1.0000x reference)
#include <cuda_runtime.h>

// TT-linear: y = x @ W^T + bias
//   c0: [1,32(o0),32(i0),4(r1)]  c1: [4(r1),16(o1),16(i1),4(r2)]  c2: [4(r2),16(o2),16(i2),1]
//
// Kernel 1: grid 256 = (token, i0-half), 256 thr = (o1,o2), 2 CTAs/SM, 16 slices/CTA.
//   One __syncthreads per slice (double-buffered A, write-then-sync-then-read ordering).
//   step1: A[i1,o2,r2] via fma2, x via shfl, conflict-free sc2[(i2*16+o2)*4+r2]
//   step2: B[r1] via 8 independent fma2 chains (depth 16), LDS.128-native operands
//   step3: yp[o0-pairs] += B via fma2, all-broadcast c0 loads
//   Low register pressure: single slice in flight (~100 regs, no spills).
// Kernel 2: out = p0 + p1 + bias; 4 float4/thread, 8 loads in flight.

#define THREADS 256

__device__ float g_scratch[2u * 128u * 8192u];  // 8 MB partials

typedef unsigned long long u64;

__device__ __forceinline__ u64 pk2(float lo, float hi) {
    u64 r;
    asm("mov.b64 %0, {%1, %2};" : "=l"(r) : "f"(lo), "f"(hi));
    return r;
}
__device__ __forceinline__ void unpk(u64 v, float& lo, float& hi) {
    asm("mov.b64 {%0, %1}, %2;" : "=f"(lo), "=f"(hi) : "l"(v));
}
__device__ __forceinline__ u64 fma2(u64 a, u64 b, u64 c) {
    u64 d;
    asm("fma.rn.f32x2 %0, %1, %2, %3;" : "=l"(d) : "l"(a), "l"(b), "l"(c));
    return d;
}
__device__ __forceinline__ float hadd(u64 v) {
    float lo, hi;
    unpk(v, lo, hi);
    return lo + hi;
}

__global__ __launch_bounds__(THREADS, 2)
void tt_partial_kernel(const float* __restrict__ x,
                       const float* __restrict__ g0,
                       const float* __restrict__ g1,
                       const float* __restrict__ g2)
{
    __shared__ __align__(16) float sc0[2048];    // [it 0..15][r1][o0]
    __shared__ __align__(16) float sc1[4096];    // [o1][i1][r1][r2]
    __shared__ __align__(16) float sc2[1024];    // [i2][o2][r2]  (conflict-free)
    __shared__ __align__(16) float sA[2][1024];  // [i1][o2][r2]

    const int tid    = threadIdx.x;
    const int token  = blockIdx.x & 127;
    const int half   = blockIdx.x >> 7;
    const int o1     = tid >> 4;          // doubles as i1 in step 1
    const int o2     = tid & 15;
    const int lane   = tid & 31;
    const int i0base = half * 16;

    // ---- core relayout into smem ----
    for (int idx = tid; idx < 2048; idx += THREADS) {
        int o0 = idx & 31, r1 = (idx >> 5) & 3, it = idx >> 7;      // it = 0..15
        sc0[idx] = g0[(o0 * 32 + i0base + it) * 4 + r1];
    }
    for (int idx = tid; idx < 4096; idx += THREADS) {
        int r2 = idx & 3, r1 = (idx >> 2) & 3, i1 = (idx >> 4) & 15, o1g = idx >> 8;
        sc1[idx] = g1[((r1 * 16 + o1g) * 16 + i1) * 4 + r2];
    }
    for (int idx = tid; idx < 1024; idx += THREADS) {
        int r2 = idx & 3, o2g = (idx >> 2) & 15, i2 = idx >> 6;
        sc2[idx] = g2[(r2 * 16 + o2g) * 16 + i2];                   // -> [(i2*16+o2)*4+r2]
    }

    const float* xrow = x + token * 8192;
    float xv = xrow[i0base * 256 + tid];   // warp lanes hold this warp's 32 x values

    u64 yp[16];                            // y[32] as packed o0 pairs
    #pragma unroll
    for (int i = 0; i < 16; i++) yp[i] = 0ull;

    const int shfl_base = lane & 16;
    const int aoff = (o1 * 16 + o2) * 4;   // this thread's A slot (as producer, i1 = o1)

    __syncthreads();

    // ---- prologue: step1 for slice 0 into buffer 0 ----
    {
        u64 a01 = 0ull, a23 = 0ull;
        #pragma unroll
        for (int i2 = 0; i2 < 16; i2++) {
            float xs = __shfl_sync(0xffffffffu, xv, shfl_base + i2);
            u64 xd = pk2(xs, xs);
            ulonglong2 c = *reinterpret_cast<const ulonglong2*>(&sc2[(i2 * 16 + o2) * 4]);
            a01 = fma2(xd, c.x, a01);
            a23 = fma2(xd, c.y, a23);
        }
        ulonglong2 st; st.x = a01; st.y = a23;
        *reinterpret_cast<ulonglong2*>(&sA[0][aoff]) = st;
    }
    float xnext = xrow[(i0base + 1) * 256 + tid];
    __syncthreads();

    for (int k = 0; k < 16; k++) {
        const float* A = sA[k & 1];

        // ---- step 2: B[r1] = sum_{i1,r2} A[i1,o2,r2]*c1[r1,o1,i1,r2]  (8 chains) ----
        u64 acc2[4][2];
        #pragma unroll
        for (int r1 = 0; r1 < 4; r1++) { acc2[r1][0] = 0ull; acc2[r1][1] = 0ull; }
        #pragma unroll
        for (int i1 = 0; i1 < 16; i1++) {
            const ulonglong2 av = *reinterpret_cast<const ulonglong2*>(
                &A[(i1 * 16 + o2) * 4]);                 // (r2 0,1),(r2 2,3)
            const ulonglong2* cp = reinterpret_cast<const ulonglong2*>(
                &sc1[(o1 * 16 + i1) * 16]);              // [r1][(r2 0,1),(r2 2,3)]
            #pragma unroll
            for (int r1 = 0; r1 < 4; r1++) {
                ulonglong2 c = cp[r1];
                acc2[r1][0] = fma2(av.x, c.x, acc2[r1][0]);
                acc2[r1][1] = fma2(av.y, c.y, acc2[r1][1]);
            }
        }
        u64 bd[4];
        #pragma unroll
        for (int r1 = 0; r1 < 4; r1++) {
            float b = hadd(acc2[r1][0]) + hadd(acc2[r1][1]);
            bd[r1] = pk2(b, b);
        }

        // ---- step 3: yp[o0-pair] += sum_r1 B[r1]*c0[k,r1,o0]  (broadcast loads) ----
        const ulonglong2* cq = reinterpret_cast<const ulonglong2*>(&sc0[k * 128]);
        #pragma unroll
        for (int q = 0; q < 8; q++) {
            #pragma unroll
            for (int r1 = 0; r1 < 4; r1++) {
                ulonglong2 c = cq[r1 * 8 + q];           // o0 = 4q..4q+3
                yp[2 * q]     = fma2(bd[r1], c.x, yp[2 * q]);
                yp[2 * q + 1] = fma2(bd[r1], c.y, yp[2 * q + 1]);
            }
        }

        // ---- step 1 for slice k+1 into the other buffer, then one sync ----
        if (k < 15) {
            xv = xnext;
            if (k < 14) xnext = xrow[(i0base + k + 2) * 256 + tid];
            u64 a01 = 0ull, a23 = 0ull;
            #pragma unroll
            for (int i2 = 0; i2 < 16; i2++) {
                float xs = __shfl_sync(0xffffffffu, xv, shfl_base + i2);
                u64 xd = pk2(xs, xs);
                ulonglong2 c = *reinterpret_cast<const ulonglong2*>(&sc2[(i2 * 16 + o2) * 4]);
                a01 = fma2(xd, c.x, a01);
                a23 = fma2(xd, c.y, a23);
            }
            ulonglong2 st; st.x = a01; st.y = a23;
            *reinterpret_cast<ulonglong2*>(&sA[(k + 1) & 1][aoff]) = st;
            __syncthreads();
        }
    }

    // ---- write partial (coalesced) ----
    float* sp = g_scratch + ((size_t)(half * 128 + token) << 13);
    #pragma unroll
    for (int q = 0; q < 8; q++) {
        float f0, f1, f2, f3;
        unpk(yp[2 * q],     f0, f1);
        unpk(yp[2 * q + 1], f2, f3);
        sp[(4 * q + 0) * 256 + tid] = f0;
        sp[(4 * q + 1) * 256 + tid] = f1;
        sp[(4 * q + 2) * 256 + tid] = f2;
        sp[(4 * q + 3) * 256 + tid] = f3;
    }
}

__global__ __launch_bounds__(128)
void tt_reduce_kernel(const float* __restrict__ bias, float* __restrict__ out)
{
    // out = 262144 float4; grid 512 x 128 thr x 4 float4/thread; 8 loads in flight
    const int base = blockIdx.x * 512 + threadIdx.x;
    const float4* s = reinterpret_cast<const float4*>(g_scratch);
    float4 a[4], b[4];
    #pragma unroll
    for (int k = 0; k < 4; k++) {
        int v = base + k * 128;
        a[k] = s[v];
        b[k] = s[v + (1 << 18)];
    }
    #pragma unroll
    for (int k = 0; k < 4; k++) {
        int v = base + k * 128;
        float4 bb = reinterpret_cast<const float4*>(bias)[v & 2047];
        float4 r;
        r.x = a[k].x + b[k].x + bb.x;
        r.y = a[k].y + b[k].y + bb.y;
        r.z = a[k].z + b[k].z + bb.z;
        r.w = a[k].w + b[k].w + bb.w;
        reinterpret_cast<float4*>(out)[v] = r;
    }
}

extern "C" void kernel_launch(void* const* d_in, const int* in_sizes, int n_in,
                              void* d_out, int out_size)
{
    const float* x    = (const float*)d_in[0];  // [128, 8192]
    const float* g0   = (const float*)d_in[1];  // [1,32,32,4]
    const float* g1   = (const float*)d_in[2];  // [4,16,16,4]
    const float* g2   = (const float*)d_in[3];  // [4,16,16,1]
    const float* bias = (const float*)d_in[4];  // [8192]
    float* out = (float*)d_out;                 // [128, 8192]

    tt_partial_kernel<<<256, THREADS>>>(x, g0, g1, g2);
    tt_reduce_kernel<<<512, 128>>>(bias, out);
}